// round 15
// baseline (speedup 1.0000x reference)
#include <cuda_runtime.h>
#include <cuda_bf16.h>
#include <mma.h>
#include <cstdint>

using namespace nvcuda;

#define T_    128
#define B_    256
#define D_    1024
#define H_    1024
#define V_    32000
#define TAGS_ 1024
#define GQ    32      // 4 gates * 8 qubits

// ---------------- scratch (static device globals; no cudaMalloc allowed) ----
__device__ float          g_embproj[V_ * GQ];           // emb @ Wg_x
__device__ __nv_bfloat16  g_lstm[(size_t)T_ * B_ * H_]; // lstm_out bf16
__device__ __nv_bfloat16  g_wtag[H_ * TAGS_];           // W_tag bf16

// ---------------- helpers ----------------------------------------------------
__device__ __forceinline__ void cp16(void* smem, const void* gmem) {
    unsigned sa = (unsigned)__cvta_generic_to_shared(smem);
    asm volatile("cp.async.cg.shared.global [%0], [%1], 16;\n" :: "r"(sa), "l"(gmem));
}
__device__ __forceinline__ float fast_sigmoid(float x) {
    return 0.5f + 0.5f * __tanhf(0.5f * x);
}
__device__ __forceinline__ float bflo(uint32_t v) { return __uint_as_float(v << 16); }
__device__ __forceinline__ float bfhi(uint32_t v) { return __uint_as_float(v & 0xffff0000u); }

// ---------------- K0: W_tag -> bf16 -----------------------------------------
__global__ void wtag_convert(const float* __restrict__ w) {
    int i = blockIdx.x * 256 + threadIdx.x;
    g_wtag[i] = __float2bfloat16(w[i]);
}

// ---------------- K1: embproj = emb @ Wg_x  via bf16 WMMA --------------------
#define EP_BS   (1024 * 40)            // B smem halves (ld = 40) = 80 KB
#define EP_AS   (256 * 72)             // A smem halves (ld = 72) = 36 KB
#define EP_SMEM (EP_BS * 2 + EP_AS * 2)

__global__ __launch_bounds__(256, 1) void embproj_kernel(const float* __restrict__ emb,
                                                         const float* __restrict__ Wg) {
    extern __shared__ char smraw[];
    __nv_bfloat16* Bs = (__nv_bfloat16*)smraw;       // [1024][40]
    __nv_bfloat16* As = Bs + EP_BS;                  // [256][72]
    float* Osm = (float*)smraw;                      // alias B region (40KB <= 80KB)

    const int tid = threadIdx.x;
    const int v0  = blockIdx.x * 256;
    const int w   = tid >> 5;

    #pragma unroll 4
    for (int i = 0; i < 128; i++) {
        int idx = tid + i * 256;
        int k = idx >> 5, gq = idx & 31;
        Bs[k * 40 + gq] = __float2bfloat16(
            Wg[(gq >> 3) * (2048 * 8) + k * 8 + (gq & 7)]);
    }

    float4 buf[16];
    #pragma unroll
    for (int i = 0; i < 16; i++) {
        int e = tid + i * 256;
        int row = e >> 4, c4 = (e & 15) * 4;
        buf[i] = *(const float4*)&emb[(size_t)(v0 + row) * D_ + c4];
    }
    __syncthreads();

    wmma::fragment<wmma::accumulator, 16, 16, 16, float> acc[2][2];
    #pragma unroll
    for (int i = 0; i < 2; i++)
        #pragma unroll
        for (int j = 0; j < 2; j++) wmma::fill_fragment(acc[i][j], 0.f);

    for (int kt = 0; kt < 16; kt++) {
        #pragma unroll
        for (int i = 0; i < 8; i++) {
            int e = tid + i * 256;
            int row = e >> 3, c8 = (e & 7) * 8;
            float4 a = buf[2 * i], b = buf[2 * i + 1];
            __nv_bfloat162 p0 = __float22bfloat162_rn(make_float2(a.x, a.y));
            __nv_bfloat162 p1 = __float22bfloat162_rn(make_float2(a.z, a.w));
            __nv_bfloat162 p2 = __float22bfloat162_rn(make_float2(b.x, b.y));
            __nv_bfloat162 p3 = __float22bfloat162_rn(make_float2(b.z, b.w));
            uint4 pk = make_uint4(*(uint32_t*)&p0, *(uint32_t*)&p1,
                                  *(uint32_t*)&p2, *(uint32_t*)&p3);
            *(uint4*)&As[row * 72 + c8] = pk;
        }
        __syncthreads();
        if (kt < 15) {
            int k0n = (kt + 1) * 64;
            #pragma unroll
            for (int i = 0; i < 16; i++) {
                int e = tid + i * 256;
                int row = e >> 4, c4 = (e & 15) * 4;
                buf[i] = *(const float4*)&emb[(size_t)(v0 + row) * D_ + k0n + c4];
            }
        }
        #pragma unroll
        for (int ks = 0; ks < 64; ks += 16) {
            wmma::fragment<wmma::matrix_a, 16, 16, 16, __nv_bfloat16, wmma::row_major> af[2];
            wmma::fragment<wmma::matrix_b, 16, 16, 16, __nv_bfloat16, wmma::row_major> bf[2];
            #pragma unroll
            for (int i = 0; i < 2; i++)
                wmma::load_matrix_sync(af[i], &As[(w * 32 + i * 16) * 72 + ks], 72);
            #pragma unroll
            for (int j = 0; j < 2; j++)
                wmma::load_matrix_sync(bf[j], &Bs[(kt * 64 + ks) * 40 + j * 16], 40);
            #pragma unroll
            for (int i = 0; i < 2; i++)
                #pragma unroll
                for (int j = 0; j < 2; j++)
                    wmma::mma_sync(acc[i][j], af[i], bf[j], acc[i][j]);
        }
        __syncthreads();
    }

    #pragma unroll
    for (int i = 0; i < 2; i++)
        #pragma unroll
        for (int j = 0; j < 2; j++)
            wmma::store_matrix_sync(&Osm[(w * 32 + i * 16) * 40 + j * 16],
                                    acc[i][j], 40, wmma::mem_row_major);
    __syncthreads();
    #pragma unroll
    for (int i = 0; i < 8; i++) {
        int e = tid + i * 256;
        int row = e >> 3, c4 = (e & 7) * 4;
        float4 o = make_float4(Osm[row * 40 + c4],     Osm[row * 40 + c4 + 1],
                               Osm[row * 40 + c4 + 2], Osm[row * 40 + c4 + 3]);
        *(float4*)&g_embproj[(size_t)(v0 + row) * GQ + c4] = o;
    }
}

// ---------------- K2: LSTM, 1 batch/CTA, 256 CTAs, 2 CTAs/SM -----------------
// 512 thr/CTA, 2 hidden units/thread (j = tid, tid+512), <=64 regs (Wp packed
// bf16x2). Two CTAs per SM overlap each other's barrier/reduce bubbles.
#define LSTM_SMEM ((16384 + 1024 + 4096 + 32) * 4)   // 86,144 B -> 2 CTA/SM

__global__ __launch_bounds__(512, 2) void lstm_kernel(
    const int*   __restrict__ sentence,
    const float* __restrict__ Wg,
    const float* __restrict__ bg,
    const float* __restrict__ theta,
    const float* __restrict__ Wp,
    const float* __restrict__ bp) {
    extern __shared__ float sm[];
    uint32_t* Wkp = (uint32_t*)sm;         // [32 gq][512 kp] bf16x2 (64 KB)
    float* h_s = sm + 16384;               // 1024
    float* xq  = h_s + 1024;               // 4096
    float* qc  = xq + 4096;                // 32 (16B aligned)

    const int tid  = threadIdx.x;
    const int warp = tid >> 5, lane = tid & 31;
    const int b    = blockIdx.x;

    // Wkp[gq][kp] = bf16x2(Wg[g][D+2kp][q], Wg[g][D+2kp+1][q])
    #pragma unroll 4
    for (int it = 0; it < 32; it++) {
        int p  = tid + it * 512;            // 16384 total
        int gq = p >> 9, kp = p & 511;
        int g  = gq >> 3, q = gq & 7;
        const float* src = Wg + g * (2048 * 8) + (size_t)(1024 + 2 * kp) * 8 + q;
        uint32_t l16 = (uint32_t)__bfloat16_as_ushort(__float2bfloat16(src[0]));
        uint32_t h16 = (uint32_t)__bfloat16_as_ushort(__float2bfloat16(src[8]));
        Wkp[gq * 512 + kp] = l16 | (h16 << 16);
    }
    // xq[t][gq] = embproj[token][gq] + bg[gq] + theta[gq]
    #pragma unroll
    for (int it = 0; it < 8; it++) {
        int p = tid + it * 512;             // 4096 total
        int t = p >> 5, gq = p & 31;
        int token = sentence[t * B_ + b];
        xq[t * 32 + gq] = g_embproj[token * GQ + gq] + bg[gq] + theta[gq];
    }
    // per-thread Wp slice packed bf16x2 (j = tid, j = tid + 512) -> 32 regs
    uint32_t wpp[32];
    float bpv[8];
    #pragma unroll
    for (int k = 0; k < 32; k++) {
        uint32_t l16 = (uint32_t)__bfloat16_as_ushort(__float2bfloat16(Wp[k * H_ + tid]));
        uint32_t h16 = (uint32_t)__bfloat16_as_ushort(__float2bfloat16(Wp[k * H_ + tid + 512]));
        wpp[k] = l16 | (h16 << 16);
    }
    #pragma unroll
    for (int g = 0; g < 4; g++) {
        bpv[g]     = bp[g * H_ + tid];
        bpv[4 + g] = bp[g * H_ + tid + 512];
    }

    h_s[tid] = 0.f; h_s[tid + 512] = 0.f;
    float ha = 0.f, hb = 0.f, ca = 0.f, cb = 0.f;
    __syncthreads();

    const int gq0 = 2 * warp, gq1 = 2 * warp + 1;
    const uint32_t* w0row = Wkp + gq0 * 512;
    const uint32_t* w1row = Wkp + gq1 * 512;
    const float2* hp = (const float2*)h_s;

    for (int t = 0; t < T_; t++) {
        // full dots for gq0/gq1 over 1024 k (lane slices k-pairs)
        float a0 = 0.f, a1 = 0.f;
        #pragma unroll
        for (int i = 0; i < 16; i++) {
            int kp = lane + 32 * i;
            uint32_t wv0 = w0row[kp];
            uint32_t wv1 = w1row[kp];
            float2 hA = hp[kp];
            a0 = fmaf(bflo(wv0), hA.x, a0); a0 = fmaf(bfhi(wv0), hA.y, a0);
            a1 = fmaf(bflo(wv1), hA.x, a1); a1 = fmaf(bfhi(wv1), hA.y, a1);
        }
        #pragma unroll
        for (int off = 16; off > 0; off >>= 1) {
            a0 += __shfl_xor_sync(~0u, a0, off);
            a1 += __shfl_xor_sync(~0u, a1, off);
        }
        if (lane == 0) {
            qc[gq0] = __cosf(a0 + xq[t * 32 + gq0]);
            qc[gq1] = __cosf(a1 + xq[t * 32 + gq1]);
        }
        __syncthreads();

        // gates for j = tid (lo) and j = tid+512 (hi), Wp unpacked from bf16x2
        float pja[4], pjb[4];
        {
            const float4* q4 = (const float4*)qc;
            #pragma unroll
            for (int g = 0; g < 4; g++) {
                float4 x = q4[2 * g], y = q4[2 * g + 1];
                float sa = bpv[g], sb = bpv[4 + g];
                uint32_t w;
                w = wpp[g * 8 + 0]; sa = fmaf(x.x, bflo(w), sa); sb = fmaf(x.x, bfhi(w), sb);
                w = wpp[g * 8 + 1]; sa = fmaf(x.y, bflo(w), sa); sb = fmaf(x.y, bfhi(w), sb);
                w = wpp[g * 8 + 2]; sa = fmaf(x.z, bflo(w), sa); sb = fmaf(x.z, bfhi(w), sb);
                w = wpp[g * 8 + 3]; sa = fmaf(x.w, bflo(w), sa); sb = fmaf(x.w, bfhi(w), sb);
                w = wpp[g * 8 + 4]; sa = fmaf(y.x, bflo(w), sa); sb = fmaf(y.x, bfhi(w), sb);
                w = wpp[g * 8 + 5]; sa = fmaf(y.y, bflo(w), sa); sb = fmaf(y.y, bfhi(w), sb);
                w = wpp[g * 8 + 6]; sa = fmaf(y.z, bflo(w), sa); sb = fmaf(y.z, bfhi(w), sb);
                w = wpp[g * 8 + 7]; sa = fmaf(y.w, bflo(w), sa); sb = fmaf(y.w, bfhi(w), sb);
                pja[g] = sa; pjb[g] = sb;
            }
        }
        float fg = fast_sigmoid(pja[0]);
        float ig = fast_sigmoid(pja[1]);
        float gg = __tanhf(pja[2]);
        float og = fast_sigmoid(pja[3]);
        ca = fg * ca + ig * gg;
        ha = og * __tanhf(ca);

        fg = fast_sigmoid(pjb[0]);
        ig = fast_sigmoid(pjb[1]);
        gg = __tanhf(pjb[2]);
        og = fast_sigmoid(pjb[3]);
        cb = fg * cb + ig * gg;
        hb = og * __tanhf(cb);

        size_t base = ((size_t)t * B_ + b) * H_;
        g_lstm[base + tid]       = __float2bfloat16(ha);
        g_lstm[base + tid + 512] = __float2bfloat16(hb);
        h_s[tid] = ha; h_s[tid + 512] = hb;
        __syncthreads();
    }
}

// ---------------- K3: fused tag GEMM (bf16 WMMA 64x64, 4 cp.async stages) ----
#define A_STG (256 * 72)     // halves per A stage (ld = 72)
#define B_STG (64 * 136)     // halves per B stage (ld = 136)
#define TAG_SMEM (4 * (A_STG + B_STG) * 2)

__global__ __launch_bounds__(256, 1) void tag_kernel(float* __restrict__ out) {
    extern __shared__ char smraw[];
    __nv_bfloat16* Asm = (__nv_bfloat16*)smraw;        // 4 stages 256x72
    __nv_bfloat16* Bsm = Asm + 4 * A_STG;              // 4 stages 64x136
    float* Osm = (float*)smraw;                        // 256 x 136 fp32 (alias)
    float* red = Osm + 256 * 136;

    const int tid = threadIdx.x;
    const int t   = blockIdx.y;
    const int c0  = blockIdx.x * 128;
    const int w   = tid >> 5;
    const int wy  = w >> 1;
    const int wx  = w & 1;

    wmma::fragment<wmma::accumulator, 16, 16, 16, float> acc[4][4];
    #pragma unroll
    for (int i = 0; i < 4; i++)
        #pragma unroll
        for (int j = 0; j < 4; j++) wmma::fill_fragment(acc[i][j], 0.f);

    auto issue_tile = [&](int kt) {
        int s  = kt & 3;
        int k0 = kt * 64;
        __nv_bfloat16* As = Asm + s * A_STG;
        __nv_bfloat16* Bs = Bsm + s * B_STG;
        #pragma unroll
        for (int i = 0; i < 8; i++) {
            int e = tid + i * 256;
            int row = e >> 3, c8 = (e & 7) * 8;
            cp16(&As[row * 72 + c8],
                 &g_lstm[((size_t)t * B_ + row) * H_ + k0 + c8]);
        }
        #pragma unroll
        for (int i = 0; i < 4; i++) {
            int e = tid + i * 256;
            int row = e >> 4, c8 = (e & 15) * 8;
            cp16(&Bs[row * 136 + c8],
                 &g_wtag[(size_t)(k0 + row) * TAGS_ + c0 + c8]);
        }
        asm volatile("cp.async.commit_group;\n" ::);
    };

    issue_tile(0);
    issue_tile(1);
    issue_tile(2);
    for (int kt = 0; kt < 16; kt++) {
        if (kt < 14)       asm volatile("cp.async.wait_group 2;\n" ::);
        else if (kt == 14) asm volatile("cp.async.wait_group 1;\n" ::);
        else               asm volatile("cp.async.wait_group 0;\n" ::);
        __syncthreads();
        int s = kt & 3;
        const __nv_bfloat16* As = Asm + s * A_STG;
        const __nv_bfloat16* Bs = Bsm + s * B_STG;
        #pragma unroll
        for (int ks = 0; ks < 64; ks += 16) {
            wmma::fragment<wmma::matrix_a, 16, 16, 16, __nv_bfloat16, wmma::row_major> af[4];
            wmma::fragment<wmma::matrix_b, 16, 16, 16, __nv_bfloat16, wmma::row_major> bf[4];
            #pragma unroll
            for (int i = 0; i < 4; i++)
                wmma::load_matrix_sync(af[i], &As[(wy * 64 + i * 16) * 72 + ks], 72);
            #pragma unroll
            for (int j = 0; j < 4; j++)
                wmma::load_matrix_sync(bf[j], &Bs[ks * 136 + wx * 64 + j * 16], 136);
            #pragma unroll
            for (int i = 0; i < 4; i++)
                #pragma unroll
                for (int j = 0; j < 4; j++)
                    wmma::mma_sync(acc[i][j], af[i], bf[j], acc[i][j]);
        }
        if (kt + 3 < 16) issue_tile(kt + 3);
    }
    __syncthreads();

    #pragma unroll
    for (int i = 0; i < 4; i++)
        #pragma unroll
        for (int j = 0; j < 4; j++)
            wmma::store_matrix_sync(&Osm[(wy * 64 + i * 16) * 136 + wx * 64 + j * 16],
                                    acc[i][j], 136, wmma::mem_row_major);
    __syncthreads();

    const int p = tid >> 7;
    const int c = tid & 127;
    float m = -1e30f;
    #pragma unroll 8
    for (int i = 0; i < 128; i++) m = fmaxf(m, Osm[(p * 128 + i) * 136 + c]);
    red[p * 128 + c] = m;
    __syncthreads();
    float M = fmaxf(red[c], red[128 + c]);
    float ssum = 0.f;
    #pragma unroll 8
    for (int i = 0; i < 128; i++) ssum += __expf(Osm[(p * 128 + i) * 136 + c] - M);
    __syncthreads();
    red[p * 128 + c] = ssum;
    __syncthreads();
    float lse = M + logf(red[c] + red[128 + c]);
    #pragma unroll 8
    for (int i = 0; i < 128; i++) {
        int b = p * 128 + i;
        out[((size_t)t * B_ + b) * TAGS_ + c0 + c] = Osm[b * 136 + c] - lse;
    }
}

// ---------------- launch -----------------------------------------------------
extern "C" void kernel_launch(void* const* d_in, const int* in_sizes, int n_in,
                              void* d_out, int out_size) {
    const int*   sentence = (const int*)  d_in[0];
    const float* emb      = (const float*)d_in[1];
    const float* Wg       = (const float*)d_in[2];
    const float* bg       = (const float*)d_in[3];
    const float* theta    = (const float*)d_in[4];
    const float* Wp       = (const float*)d_in[5];
    const float* bp       = (const float*)d_in[6];
    const float* W_tag    = (const float*)d_in[7];
    // d_in[8] = b_tag: cancels in log_softmax over batch axis -> unused
    float* out = (float*)d_out;

    cudaFuncSetAttribute(embproj_kernel, cudaFuncAttributeMaxDynamicSharedMemorySize, EP_SMEM);
    cudaFuncSetAttribute(lstm_kernel,    cudaFuncAttributeMaxDynamicSharedMemorySize, LSTM_SMEM);
    cudaFuncSetAttribute(tag_kernel,     cudaFuncAttributeMaxDynamicSharedMemorySize, TAG_SMEM);

    wtag_convert<<<(H_ * TAGS_) / 256, 256>>>(W_tag);
    embproj_kernel<<<V_ / 256, 256, EP_SMEM>>>(emb, Wg);
    lstm_kernel<<<B_, 512, LSTM_SMEM>>>(sentence, Wg, bg, theta, Wp, bp);
    dim3 g3(TAGS_ / 128, T_);
    tag_kernel<<<g3, 256, TAG_SMEM>>>(out);
}

// round 16
// speedup vs baseline: 1.2070x; 1.2070x over previous
#include <cuda_runtime.h>
#include <cuda_bf16.h>
#include <mma.h>
#include <cstdint>

using namespace nvcuda;

#define T_    128
#define B_    256
#define D_    1024
#define H_    1024
#define V_    32000
#define TAGS_ 1024
#define GQ    32      // 4 gates * 8 qubits

// ---------------- scratch (static device globals; no cudaMalloc allowed) ----
__device__ float          g_embproj[V_ * GQ];           // emb @ Wg_x
__device__ __nv_bfloat16  g_lstm[(size_t)T_ * B_ * H_]; // lstm_out bf16
__device__ __nv_bfloat16  g_wtag[H_ * TAGS_];           // W_tag bf16

// ---------------- helpers ----------------------------------------------------
__device__ __forceinline__ void cp16(void* smem, const void* gmem) {
    unsigned sa = (unsigned)__cvta_generic_to_shared(smem);
    asm volatile("cp.async.cg.shared.global [%0], [%1], 16;\n" :: "r"(sa), "l"(gmem));
}
__device__ __forceinline__ float fast_sigmoid(float x) {
    return 0.5f + 0.5f * __tanhf(0.5f * x);
}

// ---------------- K1: prep = embproj (blocks 0-124) + wtag cvt (125-252) -----
#define EP_BS   (1024 * 40)            // B smem halves (ld = 40) = 80 KB
#define EP_AS   (256 * 72)             // A smem halves (ld = 72) = 36 KB
#define EP_SMEM (EP_BS * 2 + EP_AS * 2)

__global__ __launch_bounds__(256, 1) void prep_kernel(const float* __restrict__ emb,
                                                      const float* __restrict__ Wg,
                                                      const float* __restrict__ wtag) {
    if (blockIdx.x >= 125) {
        // W_tag -> bf16: 128 blocks x 8192 elements
        int base = (blockIdx.x - 125) * 8192 + threadIdx.x;
        #pragma unroll
        for (int i = 0; i < 32; i++)
            g_wtag[base + i * 256] = __float2bfloat16(wtag[base + i * 256]);
        return;
    }
    extern __shared__ char smraw[];
    __nv_bfloat16* Bs = (__nv_bfloat16*)smraw;       // [1024][40]
    __nv_bfloat16* As = Bs + EP_BS;                  // [256][72]
    float* Osm = (float*)smraw;                      // alias B region (40KB <= 80KB)

    const int tid = threadIdx.x;
    const int v0  = blockIdx.x * 256;
    const int w   = tid >> 5;

    #pragma unroll 4
    for (int i = 0; i < 128; i++) {
        int idx = tid + i * 256;
        int k = idx >> 5, gq = idx & 31;
        Bs[k * 40 + gq] = __float2bfloat16(
            Wg[(gq >> 3) * (2048 * 8) + k * 8 + (gq & 7)]);
    }

    float4 buf[16];
    #pragma unroll
    for (int i = 0; i < 16; i++) {
        int e = tid + i * 256;
        int row = e >> 4, c4 = (e & 15) * 4;
        buf[i] = *(const float4*)&emb[(size_t)(v0 + row) * D_ + c4];
    }
    __syncthreads();

    wmma::fragment<wmma::accumulator, 16, 16, 16, float> acc[2][2];
    #pragma unroll
    for (int i = 0; i < 2; i++)
        #pragma unroll
        for (int j = 0; j < 2; j++) wmma::fill_fragment(acc[i][j], 0.f);

    for (int kt = 0; kt < 16; kt++) {
        #pragma unroll
        for (int i = 0; i < 8; i++) {
            int e = tid + i * 256;
            int row = e >> 3, c8 = (e & 7) * 8;
            float4 a = buf[2 * i], b = buf[2 * i + 1];
            __nv_bfloat162 p0 = __float22bfloat162_rn(make_float2(a.x, a.y));
            __nv_bfloat162 p1 = __float22bfloat162_rn(make_float2(a.z, a.w));
            __nv_bfloat162 p2 = __float22bfloat162_rn(make_float2(b.x, b.y));
            __nv_bfloat162 p3 = __float22bfloat162_rn(make_float2(b.z, b.w));
            uint4 pk = make_uint4(*(uint32_t*)&p0, *(uint32_t*)&p1,
                                  *(uint32_t*)&p2, *(uint32_t*)&p3);
            *(uint4*)&As[row * 72 + c8] = pk;
        }
        __syncthreads();
        if (kt < 15) {
            int k0n = (kt + 1) * 64;
            #pragma unroll
            for (int i = 0; i < 16; i++) {
                int e = tid + i * 256;
                int row = e >> 4, c4 = (e & 15) * 4;
                buf[i] = *(const float4*)&emb[(size_t)(v0 + row) * D_ + k0n + c4];
            }
        }
        #pragma unroll
        for (int ks = 0; ks < 64; ks += 16) {
            wmma::fragment<wmma::matrix_a, 16, 16, 16, __nv_bfloat16, wmma::row_major> af[2];
            wmma::fragment<wmma::matrix_b, 16, 16, 16, __nv_bfloat16, wmma::row_major> bf[2];
            #pragma unroll
            for (int i = 0; i < 2; i++)
                wmma::load_matrix_sync(af[i], &As[(w * 32 + i * 16) * 72 + ks], 72);
            #pragma unroll
            for (int j = 0; j < 2; j++)
                wmma::load_matrix_sync(bf[j], &Bs[(kt * 64 + ks) * 40 + j * 16], 40);
            #pragma unroll
            for (int i = 0; i < 2; i++)
                #pragma unroll
                for (int j = 0; j < 2; j++)
                    wmma::mma_sync(acc[i][j], af[i], bf[j], acc[i][j]);
        }
        __syncthreads();
    }

    #pragma unroll
    for (int i = 0; i < 2; i++)
        #pragma unroll
        for (int j = 0; j < 2; j++)
            wmma::store_matrix_sync(&Osm[(w * 32 + i * 16) * 40 + j * 16],
                                    acc[i][j], 40, wmma::mem_row_major);
    __syncthreads();
    #pragma unroll
    for (int i = 0; i < 8; i++) {
        int e = tid + i * 256;
        int row = e >> 3, c4 = (e & 7) * 4;
        float4 o = make_float4(Osm[row * 40 + c4],     Osm[row * 40 + c4 + 1],
                               Osm[row * 40 + c4 + 2], Osm[row * 40 + c4 + 3]);
        *(float4*)&g_embproj[(size_t)(v0 + row) * GQ + c4] = o;
    }
}

// ---------------- K2: LSTM with tensor-core Wh matvec ------------------------
// 512 thr/CTA, 2 batches/CTA (A rows 0,1; rows 2-15 zero-padded), 128 CTAs.
// Warp w: N-half (w&1), K-slice 128 (w>>1). Wh bf16 in smem; qraw partials
// reduced across 8 K-slice warps via fp32 smem tile.
// smem bytes: A_s 16x1040 bf16 (33280) | Bs 1024x40 bf16 (81920)
//             | Psm 16x16x20 f32 (20480) | xq0/1 (32768) | qc0/1 (256)
#define LDA 1040
#define LSTM_SMEM (33280 + 81920 + 20480 + 32768 + 256)   // 168,704 B

__device__ __forceinline__ void gate_update(const float4* qc, const float* wp,
                                            const float* bpv, float& c, float& h) {
    float pj[4];
    #pragma unroll
    for (int g = 0; g < 4; g++) {
        float4 a = qc[2 * g], b = qc[2 * g + 1];
        float s = bpv[g];
        s = fmaf(a.x, wp[g * 8 + 0], s); s = fmaf(a.y, wp[g * 8 + 1], s);
        s = fmaf(a.z, wp[g * 8 + 2], s); s = fmaf(a.w, wp[g * 8 + 3], s);
        s = fmaf(b.x, wp[g * 8 + 4], s); s = fmaf(b.y, wp[g * 8 + 5], s);
        s = fmaf(b.z, wp[g * 8 + 6], s); s = fmaf(b.w, wp[g * 8 + 7], s);
        pj[g] = s;
    }
    float fg = fast_sigmoid(pj[0]);
    float ig = fast_sigmoid(pj[1]);
    float gg = __tanhf(pj[2]);
    float og = fast_sigmoid(pj[3]);
    c = fg * c + ig * gg;
    h = og * __tanhf(c);
}

__global__ __launch_bounds__(512, 1) void lstm_kernel(
    const int*   __restrict__ sentence,
    const float* __restrict__ Wg,
    const float* __restrict__ bg,
    const float* __restrict__ theta,
    const float* __restrict__ Wp,
    const float* __restrict__ bp) {
    extern __shared__ char smb[];
    __nv_bfloat16* A_s = (__nv_bfloat16*)smb;                 // [16][1040]
    __nv_bfloat16* Bs  = (__nv_bfloat16*)(smb + 33280);       // [1024][40]
    float* Psm = (float*)(smb + 115200);                      // [16][16][20]
    float* xq0 = (float*)(smb + 135680);                      // [128][32]
    float* xq1 = (float*)(smb + 152064);
    float* qc0 = (float*)(smb + 168448);                      // 32 (16B aligned)
    float* qc1 = (float*)(smb + 168576);

    const int tid  = threadIdx.x;
    const int warp = tid >> 5;
    const int b0   = blockIdx.x * 2;

    // zero A tile (rows 2-15 stay zero forever)
    for (int i = tid; i < 8320; i += 512) ((uint32_t*)A_s)[i] = 0;

    // Bs[k][gq] = Wg[g][D + k][q] bf16   (32768 elems, 64/thread)
    #pragma unroll 4
    for (int it = 0; it < 64; it++) {
        int p = tid + it * 512;
        int k = p >> 5, gq = p & 31;
        Bs[k * 40 + gq] = __float2bfloat16(
            Wg[(gq >> 3) * (2048 * 8) + (size_t)(1024 + k) * 8 + (gq & 7)]);
    }
    // xq[b][t][gq] = embproj[token][gq] + bg[gq] + theta[gq]
    #pragma unroll
    for (int it = 0; it < 16; it++) {
        int p  = tid + it * 512;
        int bb = p >> 12, r = p & 4095;
        int t  = r >> 5, gq = r & 31;
        int token = sentence[t * B_ + b0 + bb];
        (bb ? xq1 : xq0)[t * 32 + gq] =
            g_embproj[token * GQ + gq] + bg[gq] + theta[gq];
    }
    // per-thread Wp slices (j = tid, j = tid + 512)
    float wpreg[64], bpv[8];
    #pragma unroll
    for (int k = 0; k < 32; k++) {
        wpreg[k]      = Wp[k * H_ + tid];
        wpreg[32 + k] = Wp[k * H_ + tid + 512];
    }
    #pragma unroll
    for (int g = 0; g < 4; g++) {
        bpv[g]     = bp[g * H_ + tid];
        bpv[4 + g] = bp[g * H_ + tid + 512];
    }

    float h0a = 0.f, h0b = 0.f, h1a = 0.f, h1b = 0.f;
    float c0a = 0.f, c0b = 0.f, c1a = 0.f, c1b = 0.f;
    __syncthreads();

    const int n0  = (warp & 1) * 16;     // output column half
    const int ks0 = (warp >> 1) * 128;   // K slice

    for (int t = 0; t < T_; t++) {
        // store h (bf16) into A rows 0,1
        A_s[tid]             = __float2bfloat16(h0a);
        A_s[tid + 512]       = __float2bfloat16(h0b);
        A_s[LDA + tid]       = __float2bfloat16(h1a);
        A_s[LDA + tid + 512] = __float2bfloat16(h1b);
        __syncthreads();

        // 16x16 output tile over this warp's K slice (8 MMAs)
        wmma::fragment<wmma::accumulator, 16, 16, 16, float> acc;
        wmma::fill_fragment(acc, 0.f);
        #pragma unroll
        for (int i = 0; i < 8; i++) {
            wmma::fragment<wmma::matrix_a, 16, 16, 16, __nv_bfloat16, wmma::row_major> af;
            wmma::fragment<wmma::matrix_b, 16, 16, 16, __nv_bfloat16, wmma::row_major> bf;
            wmma::load_matrix_sync(af, A_s + ks0 + 16 * i, LDA);
            wmma::load_matrix_sync(bf, Bs + (ks0 + 16 * i) * 40 + n0, 40);
            wmma::mma_sync(acc, af, bf, acc);
        }
        wmma::store_matrix_sync(Psm + warp * 320, acc, 20, wmma::mem_row_major);
        __syncthreads();

        // reduce 8 K-slice partials, add xq, cos (64 threads)
        if (tid < 64) {
            int b = tid >> 5, n = tid & 31;
            int g = n >> 4, m = n & 15;
            float s = 0.f;
            #pragma unroll
            for (int k = 0; k < 8; k++)
                s += Psm[(2 * k + g) * 320 + b * 20 + m];
            float v = __cosf(s + (b ? xq1 : xq0)[t * 32 + n]);
            (b ? qc1 : qc0)[n] = v;
        }
        __syncthreads();

        const float4* q0 = (const float4*)qc0;
        const float4* q1 = (const float4*)qc1;
        gate_update(q0, wpreg,      bpv,     c0a, h0a);
        gate_update(q0, wpreg + 32, bpv + 4, c0b, h0b);
        gate_update(q1, wpreg,      bpv,     c1a, h1a);
        gate_update(q1, wpreg + 32, bpv + 4, c1b, h1b);

        size_t base = ((size_t)t * B_ + b0) * H_;
        g_lstm[base + tid]            = __float2bfloat16(h0a);
        g_lstm[base + tid + 512]      = __float2bfloat16(h0b);
        g_lstm[base + H_ + tid]       = __float2bfloat16(h1a);
        g_lstm[base + H_ + tid + 512] = __float2bfloat16(h1b);
    }
}

// ---------------- K3: fused tag GEMM (bf16 WMMA 64x64, 4 cp.async stages) ----
#define A_STG (256 * 72)     // halves per A stage (ld = 72)
#define B_STG (64 * 136)     // halves per B stage (ld = 136)
#define TAG_SMEM (4 * (A_STG + B_STG) * 2)

__global__ __launch_bounds__(256, 1) void tag_kernel(float* __restrict__ out) {
    extern __shared__ char smraw[];
    __nv_bfloat16* Asm = (__nv_bfloat16*)smraw;        // 4 stages 256x72
    __nv_bfloat16* Bsm = Asm + 4 * A_STG;              // 4 stages 64x136
    float* Osm = (float*)smraw;                        // 256 x 136 fp32 (alias)
    float* red = Osm + 256 * 136;

    const int tid = threadIdx.x;
    const int t   = blockIdx.y;
    const int c0  = blockIdx.x * 128;
    const int w   = tid >> 5;
    const int wy  = w >> 1;
    const int wx  = w & 1;

    wmma::fragment<wmma::accumulator, 16, 16, 16, float> acc[4][4];
    #pragma unroll
    for (int i = 0; i < 4; i++)
        #pragma unroll
        for (int j = 0; j < 4; j++) wmma::fill_fragment(acc[i][j], 0.f);

    auto issue_tile = [&](int kt) {
        int s  = kt & 3;
        int k0 = kt * 64;
        __nv_bfloat16* As = Asm + s * A_STG;
        __nv_bfloat16* Bs = Bsm + s * B_STG;
        #pragma unroll
        for (int i = 0; i < 8; i++) {
            int e = tid + i * 256;
            int row = e >> 3, c8 = (e & 7) * 8;
            cp16(&As[row * 72 + c8],
                 &g_lstm[((size_t)t * B_ + row) * H_ + k0 + c8]);
        }
        #pragma unroll
        for (int i = 0; i < 4; i++) {
            int e = tid + i * 256;
            int row = e >> 4, c8 = (e & 15) * 8;
            cp16(&Bs[row * 136 + c8],
                 &g_wtag[(size_t)(k0 + row) * TAGS_ + c0 + c8]);
        }
        asm volatile("cp.async.commit_group;\n" ::);
    };

    issue_tile(0);
    issue_tile(1);
    issue_tile(2);
    for (int kt = 0; kt < 16; kt++) {
        if (kt < 14)       asm volatile("cp.async.wait_group 2;\n" ::);
        else if (kt == 14) asm volatile("cp.async.wait_group 1;\n" ::);
        else               asm volatile("cp.async.wait_group 0;\n" ::);
        __syncthreads();
        int s = kt & 3;
        const __nv_bfloat16* As = Asm + s * A_STG;
        const __nv_bfloat16* Bs = Bsm + s * B_STG;
        #pragma unroll
        for (int ks = 0; ks < 64; ks += 16) {
            wmma::fragment<wmma::matrix_a, 16, 16, 16, __nv_bfloat16, wmma::row_major> af[4];
            wmma::fragment<wmma::matrix_b, 16, 16, 16, __nv_bfloat16, wmma::row_major> bf[4];
            #pragma unroll
            for (int i = 0; i < 4; i++)
                wmma::load_matrix_sync(af[i], &As[(wy * 64 + i * 16) * 72 + ks], 72);
            #pragma unroll
            for (int j = 0; j < 4; j++)
                wmma::load_matrix_sync(bf[j], &Bs[ks * 136 + wx * 64 + j * 16], 136);
            #pragma unroll
            for (int i = 0; i < 4; i++)
                #pragma unroll
                for (int j = 0; j < 4; j++)
                    wmma::mma_sync(acc[i][j], af[i], bf[j], acc[i][j]);
        }
        if (kt + 3 < 16) issue_tile(kt + 3);
    }
    __syncthreads();

    #pragma unroll
    for (int i = 0; i < 4; i++)
        #pragma unroll
        for (int j = 0; j < 4; j++)
            wmma::store_matrix_sync(&Osm[(wy * 64 + i * 16) * 136 + wx * 64 + j * 16],
                                    acc[i][j], 136, wmma::mem_row_major);
    __syncthreads();

    const int p = tid >> 7;
    const int c = tid & 127;
    float m = -1e30f;
    #pragma unroll 8
    for (int i = 0; i < 128; i++) m = fmaxf(m, Osm[(p * 128 + i) * 136 + c]);
    red[p * 128 + c] = m;
    __syncthreads();
    float M = fmaxf(red[c], red[128 + c]);
    float ssum = 0.f;
    #pragma unroll 8
    for (int i = 0; i < 128; i++) ssum += __expf(Osm[(p * 128 + i) * 136 + c] - M);
    __syncthreads();
    red[p * 128 + c] = ssum;
    __syncthreads();
    float lse = M + logf(red[c] + red[128 + c]);
    #pragma unroll 8
    for (int i = 0; i < 128; i++) {
        int b = p * 128 + i;
        out[((size_t)t * B_ + b) * TAGS_ + c0 + c] = Osm[b * 136 + c] - lse;
    }
}

// ---------------- launch -----------------------------------------------------
extern "C" void kernel_launch(void* const* d_in, const int* in_sizes, int n_in,
                              void* d_out, int out_size) {
    const int*   sentence = (const int*)  d_in[0];
    const float* emb      = (const float*)d_in[1];
    const float* Wg       = (const float*)d_in[2];
    const float* bg       = (const float*)d_in[3];
    const float* theta    = (const float*)d_in[4];
    const float* Wp       = (const float*)d_in[5];
    const float* bp       = (const float*)d_in[6];
    const float* W_tag    = (const float*)d_in[7];
    // d_in[8] = b_tag: cancels in log_softmax over batch axis -> unused
    float* out = (float*)d_out;

    cudaFuncSetAttribute(prep_kernel, cudaFuncAttributeMaxDynamicSharedMemorySize, EP_SMEM);
    cudaFuncSetAttribute(lstm_kernel, cudaFuncAttributeMaxDynamicSharedMemorySize, LSTM_SMEM);
    cudaFuncSetAttribute(tag_kernel,  cudaFuncAttributeMaxDynamicSharedMemorySize, TAG_SMEM);

    prep_kernel<<<125 + 128, 256, EP_SMEM>>>(emb, Wg, W_tag);
    lstm_kernel<<<B_ / 2, 512, LSTM_SMEM>>>(sentence, Wg, bg, theta, Wp, bp);
    dim3 g3(TAGS_ / 128, T_);
    tag_kernel<<<g3, 256, TAG_SMEM>>>(out);
}